// round 13
// baseline (speedup 1.0000x reference)
#include <cuda_runtime.h>

#define NN    50000
#define FIN   128
#define HID   16
#define EMAX  800000
#define CHUNK 16

// Scratch — referenced ONLY inside kernel bodies (never as host-side args!)
static __device__ int   g_cnt   [NN];
static __device__ int   g_cursor[NN];
static __device__ int   g_rowptr[NN + 1];
static __device__ int   g_srcl  [EMAX];
static __device__ int   g_dstl  [EMAX];
static __device__ float g_dinv  [NN];
static __device__ float g_h1s   [NN * HID];  // (x@W1) * dinv[node]
static __device__ float g_agg1  [NN * HID];
static __device__ float g_h2s   [NN * HID];  // relu(...) * dinv[node]
static __device__ float g_agg2  [NN * HID];

// ---------------------------------------------------------------------------
__device__ __forceinline__ void red_add_v4(float* addr, float4 v) {
    asm volatile("red.global.add.v4.f32 [%0], {%1, %2, %3, %4};"
                 :: "l"(addr), "f"(v.x), "f"(v.y), "f"(v.z), "f"(v.w)
                 : "memory");
}

// ---------------------------------------------------------------------------
// 1) zero: cnt, cursor, agg1, agg2
__global__ void k_init() {
    int i = blockIdx.x * blockDim.x + threadIdx.x;
    if (i < NN) { g_cnt[i] = 0; g_cursor[i] = 0; }
    if (i < NN * HID) { g_agg1[i] = 0.f; g_agg2[i] = 0.f; }
}

// 2) histogram of dst (row 1 of int32 [2,E]) — 4 edges/thread via int4
__global__ void k_hist(const int* __restrict__ ei) {
    int t = blockIdx.x * blockDim.x + threadIdx.x;
    if (t >= EMAX / 4) return;
    int4 d4 = __ldg((const int4*)(ei + EMAX) + t);
    if ((unsigned)d4.x < (unsigned)NN) atomicAdd(&g_cnt[d4.x], 1);
    if ((unsigned)d4.y < (unsigned)NN) atomicAdd(&g_cnt[d4.y], 1);
    if ((unsigned)d4.z < (unsigned)NN) atomicAdd(&g_cnt[d4.z], 1);
    if ((unsigned)d4.w < (unsigned)NN) atomicAdd(&g_cnt[d4.w], 1);
}

// 3) exclusive prefix sum over cnt -> rowptr ; dinv = rsqrt(1 + cnt)
//    Single block, 1024 threads, chunked + Hillis-Steele block scan.
__global__ __launch_bounds__(1024) void k_scan() {
    __shared__ int part[1024];
    const int CH = (NN + 1023) / 1024;   // 49
    int tid = threadIdx.x;
    int base = tid * CH;

    int sum = 0;
    for (int i = 0; i < CH; i++) {
        int idx = base + i;
        if (idx < NN) sum += g_cnt[idx];
    }
    part[tid] = sum;
    __syncthreads();
    for (int off = 1; off < 1024; off <<= 1) {
        int add = (tid >= off) ? part[tid - off] : 0;
        __syncthreads();
        part[tid] += add;
        __syncthreads();
    }
    int run = part[tid] - sum;           // exclusive prefix of this chunk
    for (int i = 0; i < CH; i++) {
        int idx = base + i;
        if (idx < NN) {
            int c = g_cnt[idx];
            g_rowptr[idx] = run;
            g_dinv[idx] = rsqrtf(1.0f + (float)c);
            run += c;
        }
    }
    if (tid == 1023) g_rowptr[NN] = run;
}

// 4) reorder edges into dst-sorted slots
__global__ void k_reorder(const int* __restrict__ ei) {
    int e = blockIdx.x * blockDim.x + threadIdx.x;
    if (e >= EMAX) return;
    int s = ei[e];
    int d = ei[EMAX + e];
    if ((unsigned)s >= (unsigned)NN || (unsigned)d >= (unsigned)NN) return;
    int pos = g_rowptr[d] + atomicAdd(&g_cursor[d], 1);
    g_srcl[pos] = s;
    g_dstl[pos] = d;
}

// ---------------------------------------------------------------------------
// 5) h1s = (x @ W1) * dinv — tiled, 32 nodes / 256-thread block (R12 proven)
#define XS_STRIDE 132
__global__ __launch_bounds__(256) void k_mm1(const float* __restrict__ x,
                                             const float* __restrict__ W1) {
    __shared__ float xs[32 * XS_STRIDE];
    __shared__ float ws[FIN * HID];
    int node0 = blockIdx.x * 32;
    int tid = threadIdx.x;

    for (int i4 = tid; i4 < FIN * HID / 4; i4 += 256)
        ((float4*)ws)[i4] = __ldg((const float4*)W1 + i4);
    for (int i4 = tid; i4 < 32 * FIN / 4; i4 += 256) {
        int row = i4 >> 5, col4 = i4 & 31;
        int node = node0 + row;
        float4 v = (node < NN) ? __ldg((const float4*)(x + (size_t)node * FIN) + col4)
                               : make_float4(0.f, 0.f, 0.f, 0.f);
        *(float4*)&xs[row * XS_STRIDE + col4 * 4] = v;
    }
    __syncthreads();

    int n = tid >> 3, og = tid & 7;
    int o0 = og * 2;
    float acc0 = 0.f, acc1 = 0.f;
    #pragma unroll
    for (int k4 = 0; k4 < FIN / 4; k4++) {
        float4 xv = *(const float4*)&xs[n * XS_STRIDE + k4 * 4];
        float2 w0 = *(const float2*)&ws[(k4 * 4 + 0) * HID + o0];
        float2 w1 = *(const float2*)&ws[(k4 * 4 + 1) * HID + o0];
        float2 w2 = *(const float2*)&ws[(k4 * 4 + 2) * HID + o0];
        float2 w3 = *(const float2*)&ws[(k4 * 4 + 3) * HID + o0];
        acc0 += xv.x * w0.x + xv.y * w1.x + xv.z * w2.x + xv.w * w3.x;
        acc1 += xv.x * w0.y + xv.y * w1.y + xv.z * w2.y + xv.w * w3.y;
    }
    int node = node0 + n;
    if (node < NN) {
        float dv = g_dinv[node];
        g_h1s[node * HID + o0]     = acc0 * dv;
        g_h1s[node * HID + o0 + 1] = acc1 * dv;
    }
}

// ---------------------------------------------------------------------------
// 6/8) segmented gather-reduce over dst-sorted slots.
//      4 threads per 16-slot chunk; thread q owns feature quarter q.
//      Flush red.v4 only at segment boundaries (~0.5 atomics/edge).
__global__ void k_gath1() {
    int t = blockIdx.x * blockDim.x + threadIdx.x;
    int gchunk = t >> 2, q = t & 3;
    int s0 = gchunk * CHUNK;
    if (s0 >= EMAX) return;
    int send = min(s0 + CHUNK, EMAX);

    int cur = g_dstl[s0];
    float4 acc = make_float4(0.f, 0.f, 0.f, 0.f);
    for (int slot = s0; slot < send; slot++) {
        int d = g_dstl[slot];
        if (d != cur) {
            red_add_v4((float*)((float4*)(g_agg1 + (size_t)cur * HID) + q), acc);
            acc = make_float4(0.f, 0.f, 0.f, 0.f);
            cur = d;
        }
        int s = g_srcl[slot];
        float4 v = ((const float4*)(g_h1s + (size_t)s * HID))[q];
        acc.x += v.x; acc.y += v.y; acc.z += v.z; acc.w += v.w;
    }
    red_add_v4((float*)((float4*)(g_agg1 + (size_t)cur * HID) + q), acc);
}

__global__ void k_gath2() {
    int t = blockIdx.x * blockDim.x + threadIdx.x;
    int gchunk = t >> 2, q = t & 3;
    int s0 = gchunk * CHUNK;
    if (s0 >= EMAX) return;
    int send = min(s0 + CHUNK, EMAX);

    int cur = g_dstl[s0];
    float4 acc = make_float4(0.f, 0.f, 0.f, 0.f);
    for (int slot = s0; slot < send; slot++) {
        int d = g_dstl[slot];
        if (d != cur) {
            red_add_v4((float*)((float4*)(g_agg2 + (size_t)cur * HID) + q), acc);
            acc = make_float4(0.f, 0.f, 0.f, 0.f);
            cur = d;
        }
        int s = g_srcl[slot];
        float4 v = ((const float4*)(g_h2s + (size_t)s * HID))[q];
        acc.x += v.x; acc.y += v.y; acc.z += v.z; acc.w += v.w;
    }
    red_add_v4((float*)((float4*)(g_agg2 + (size_t)cur * HID) + q), acc);
}

// ---------------------------------------------------------------------------
// 7) h2s = relu(dinv*(agg1 + h1s) + b1) * dinv
__global__ void k_relu(const float* __restrict__ b1) {
    int i = blockIdx.x * blockDim.x + threadIdx.x;
    if (i < NN * HID) {
        int node = i >> 4, f = i & 15;
        float di = g_dinv[node];
        float t = di * (g_agg1[i] + g_h1s[i]) + __ldg(&b1[f]);
        g_h2s[i] = fmaxf(t, 0.f) * di;
    }
}

// ---------------------------------------------------------------------------
// 9) out = (dinv*(agg2 + h2s)) @ W2 + b2 — 64 nodes / 512-thread block (R12)
#define VS_STRIDE 17
__global__ __launch_bounds__(512) void k_out(const float* __restrict__ W2,
                                             const float* __restrict__ b2,
                                             float* __restrict__ out) {
    __shared__ float wsh[HID * FIN];
    __shared__ float vsh[64 * VS_STRIDE];
    __shared__ float b2s[FIN];
    int node0 = blockIdx.x * 64;
    int tid = threadIdx.x;

    for (int i4 = tid; i4 < HID * FIN / 4; i4 += 512)
        ((float4*)wsh)[i4] = __ldg((const float4*)W2 + i4);
    if (tid < FIN) b2s[tid] = __ldg(&b2[tid]);
    for (int i = tid; i < 64 * HID; i += 512) {
        int nl = i >> 4, f = i & 15;
        int node = node0 + nl;
        float v = 0.f;
        if (node < NN) {
            int gi = node * HID + f;
            v = g_dinv[node] * (g_agg2[gi] + g_h2s[gi]);
        }
        vsh[nl * VS_STRIDE + f] = v;
    }
    __syncthreads();

    int n = tid >> 3, og = tid & 7;
    int node = node0 + n;
    if (node >= NN) return;

    float acc[4][4];
    #pragma unroll
    for (int j = 0; j < 4; j++)
        #pragma unroll
        for (int i = 0; i < 4; i++)
            acc[j][i] = b2s[og * 4 + 32 * j + i];

    #pragma unroll
    for (int k = 0; k < HID; k++) {
        float v = vsh[n * VS_STRIDE + k];
        #pragma unroll
        for (int j = 0; j < 4; j++) {
            float4 w = *(const float4*)&wsh[k * FIN + og * 4 + 32 * j];
            acc[j][0] += v * w.x;  acc[j][1] += v * w.y;
            acc[j][2] += v * w.z;  acc[j][3] += v * w.w;
        }
    }
    float* orow = out + (size_t)node * FIN;
    #pragma unroll
    for (int j = 0; j < 4; j++)
        *(float4*)&orow[og * 4 + 32 * j] =
            make_float4(acc[j][0], acc[j][1], acc[j][2], acc[j][3]);
}

// ---------------------------------------------------------------------------
extern "C" void kernel_launch(void* const* d_in, const int* in_sizes, int n_in,
                              void* d_out, int out_size) {
    // Binding proven in R9: 0:x  1:edge_index(int32 [2,E])  2:W1  3:b1  4:W2  5:b2
    const float* x  = (const float*)d_in[0];
    const int*   ei = (const int*)d_in[1];
    const float* W1 = (const float*)d_in[2];
    const float* b1 = (const float*)d_in[3];
    const float* W2 = (const float*)d_in[4];
    const float* b2 = (const float*)d_in[5];
    float* out = (float*)d_out;

    int nchunks = (EMAX + CHUNK - 1) / CHUNK;          // 50000
    int gath_threads = nchunks * 4;                    // 200000

    k_init   <<<(NN * HID + 255) / 256, 256>>>();
    k_hist   <<<(EMAX / 4 + 255) / 256, 256>>>(ei);
    k_scan   <<<1, 1024>>>();
    k_reorder<<<(EMAX + 255) / 256, 256>>>(ei);
    k_mm1    <<<(NN + 31) / 32, 256>>>(x, W1);
    k_gath1  <<<(gath_threads + 255) / 256, 256>>>();
    k_relu   <<<(NN * HID + 255) / 256, 256>>>(b1);
    k_gath2  <<<(gath_threads + 255) / 256, 256>>>();
    k_out    <<<(NN + 63) / 64, 512>>>(W2, b2, out);
}

// round 14
// speedup vs baseline: 2.1176x; 2.1176x over previous
#include <cuda_runtime.h>

#define NN   50000
#define FIN  128
#define HID  16
#define EMAX 800000

// Scratch — referenced ONLY inside kernel bodies (never as host-side args!)
static __device__ float g_deg [NN];
static __device__ float g_dinv[NN];
static __device__ float g_h1s [NN * HID];   // (x@W1) * dinv[node]
static __device__ float g_agg1[NN * HID];
static __device__ float g_h2s [NN * HID];   // relu(...) * dinv[node]
static __device__ float g_agg2[NN * HID];

// ---------------------------------------------------------------------------
__device__ __forceinline__ void red_add_v4(float* addr, float4 v) {
    asm volatile("red.global.add.v4.f32 [%0], {%1, %2, %3, %4};"
                 :: "l"(addr), "f"(v.x), "f"(v.y), "f"(v.z), "f"(v.w)
                 : "memory");
}

// ---------------------------------------------------------------------------
// 1) deg = 1 (self loop); zero both accumulators — float4 stores
__global__ void k_init() {
    int i = blockIdx.x * blockDim.x + threadIdx.x;
    if (i < NN) g_deg[i] = 1.0f;
    if (i < NN * HID / 4) {
        ((float4*)g_agg1)[i] = make_float4(0.f, 0.f, 0.f, 0.f);
        ((float4*)g_agg2)[i] = make_float4(0.f, 0.f, 0.f, 0.f);
    }
}

// 2) in-degree over dst (row 1 of int32 [2,E]) — 4 edges/thread via int4
__global__ void k_deg(const int* __restrict__ ei) {
    int t = blockIdx.x * blockDim.x + threadIdx.x;
    if (t >= EMAX / 4) return;
    int4 d4 = __ldg((const int4*)(ei + EMAX) + t);
    if ((unsigned)d4.x < (unsigned)NN) atomicAdd(&g_deg[d4.x], 1.0f);
    if ((unsigned)d4.y < (unsigned)NN) atomicAdd(&g_deg[d4.y], 1.0f);
    if ((unsigned)d4.z < (unsigned)NN) atomicAdd(&g_deg[d4.z], 1.0f);
    if ((unsigned)d4.w < (unsigned)NN) atomicAdd(&g_deg[d4.w], 1.0f);
}

// ---------------------------------------------------------------------------
// 3) h1s = (x @ W1) * dinv ; also stores dinv = rsqrt(deg).  (R12 proven)
#define XS_STRIDE 132
__global__ __launch_bounds__(256) void k_mm1(const float* __restrict__ x,
                                             const float* __restrict__ W1) {
    __shared__ float xs[32 * XS_STRIDE];
    __shared__ float ws[FIN * HID];
    __shared__ float dvs[32];
    int node0 = blockIdx.x * 32;
    int tid = threadIdx.x;

    for (int i4 = tid; i4 < FIN * HID / 4; i4 += 256)
        ((float4*)ws)[i4] = __ldg((const float4*)W1 + i4);
    for (int i4 = tid; i4 < 32 * FIN / 4; i4 += 256) {
        int row = i4 >> 5, col4 = i4 & 31;
        int node = node0 + row;
        float4 v = (node < NN) ? __ldg((const float4*)(x + (size_t)node * FIN) + col4)
                               : make_float4(0.f, 0.f, 0.f, 0.f);
        *(float4*)&xs[row * XS_STRIDE + col4 * 4] = v;
    }
    if (tid < 32) {
        int node = node0 + tid;
        float d = (node < NN) ? rsqrtf(g_deg[node]) : 0.f;
        dvs[tid] = d;
        if (node < NN) g_dinv[node] = d;
    }
    __syncthreads();

    int n = tid >> 3, og = tid & 7;
    int o0 = og * 2;
    float acc0 = 0.f, acc1 = 0.f;
    #pragma unroll
    for (int k4 = 0; k4 < FIN / 4; k4++) {
        float4 xv = *(const float4*)&xs[n * XS_STRIDE + k4 * 4];
        float2 w0 = *(const float2*)&ws[(k4 * 4 + 0) * HID + o0];
        float2 w1 = *(const float2*)&ws[(k4 * 4 + 1) * HID + o0];
        float2 w2 = *(const float2*)&ws[(k4 * 4 + 2) * HID + o0];
        float2 w3 = *(const float2*)&ws[(k4 * 4 + 3) * HID + o0];
        acc0 += xv.x * w0.x + xv.y * w1.x + xv.z * w2.x + xv.w * w3.x;
        acc1 += xv.x * w0.y + xv.y * w1.y + xv.z * w2.y + xv.w * w3.y;
    }
    int node = node0 + n;
    if (node < NN) {
        float dv = dvs[n];
        g_h1s[node * HID + o0]     = acc0 * dv;
        g_h1s[node * HID + o0 + 1] = acc1 * dv;
    }
}

// ---------------------------------------------------------------------------
// 4) layer-1 scatter: agg1[dst] += h1s[src]
//    4 edges per thread, one feature quarter each; front-batched loads (MLP=4).
__global__ void k_scat1(const int* __restrict__ ei) {
    int t = blockIdx.x * blockDim.x + threadIdx.x;
    int q = t & 3;
    int g = t >> 2;                 // edge group, 4 edges each
    if (g >= EMAX / 4) return;
    int4 s4 = __ldg((const int4*)ei + g);
    int4 d4 = __ldg((const int4*)(ei + EMAX) + g);
    float4 v0 = ((const float4*)(g_h1s + (size_t)s4.x * HID))[q];
    float4 v1 = ((const float4*)(g_h1s + (size_t)s4.y * HID))[q];
    float4 v2 = ((const float4*)(g_h1s + (size_t)s4.z * HID))[q];
    float4 v3 = ((const float4*)(g_h1s + (size_t)s4.w * HID))[q];
    red_add_v4((float*)((float4*)(g_agg1 + (size_t)d4.x * HID) + q), v0);
    red_add_v4((float*)((float4*)(g_agg1 + (size_t)d4.y * HID) + q), v1);
    red_add_v4((float*)((float4*)(g_agg1 + (size_t)d4.z * HID) + q), v2);
    red_add_v4((float*)((float4*)(g_agg1 + (size_t)d4.w * HID) + q), v3);
}

// ---------------------------------------------------------------------------
// 5) h2s = relu(dinv*(agg1 + h1s) + b1) * dinv
__global__ void k_relu(const float* __restrict__ b1) {
    int i = blockIdx.x * blockDim.x + threadIdx.x;
    if (i < NN * HID) {
        int node = i >> 4, f = i & 15;
        float di = g_dinv[node];
        float t = di * (g_agg1[i] + g_h1s[i]) + __ldg(&b1[f]);
        g_h2s[i] = fmaxf(t, 0.f) * di;
    }
}

// ---------------------------------------------------------------------------
// 6) layer-2 scatter: agg2[dst] += h2s[src] — same scheme
__global__ void k_scat2(const int* __restrict__ ei) {
    int t = blockIdx.x * blockDim.x + threadIdx.x;
    int q = t & 3;
    int g = t >> 2;
    if (g >= EMAX / 4) return;
    int4 s4 = __ldg((const int4*)ei + g);
    int4 d4 = __ldg((const int4*)(ei + EMAX) + g);
    float4 v0 = ((const float4*)(g_h2s + (size_t)s4.x * HID))[q];
    float4 v1 = ((const float4*)(g_h2s + (size_t)s4.y * HID))[q];
    float4 v2 = ((const float4*)(g_h2s + (size_t)s4.z * HID))[q];
    float4 v3 = ((const float4*)(g_h2s + (size_t)s4.w * HID))[q];
    red_add_v4((float*)((float4*)(g_agg2 + (size_t)d4.x * HID) + q), v0);
    red_add_v4((float*)((float4*)(g_agg2 + (size_t)d4.y * HID) + q), v1);
    red_add_v4((float*)((float4*)(g_agg2 + (size_t)d4.z * HID) + q), v2);
    red_add_v4((float*)((float4*)(g_agg2 + (size_t)d4.w * HID) + q), v3);
}

// ---------------------------------------------------------------------------
// 7) out = (dinv*(agg2 + h2s)) @ W2 + b2 — 64 nodes / 512-thread block (R12)
#define VS_STRIDE 17
__global__ __launch_bounds__(512) void k_out(const float* __restrict__ W2,
                                             const float* __restrict__ b2,
                                             float* __restrict__ out) {
    __shared__ float wsh[HID * FIN];
    __shared__ float vsh[64 * VS_STRIDE];
    __shared__ float b2s[FIN];
    int node0 = blockIdx.x * 64;
    int tid = threadIdx.x;

    for (int i4 = tid; i4 < HID * FIN / 4; i4 += 512)
        ((float4*)wsh)[i4] = __ldg((const float4*)W2 + i4);
    if (tid < FIN) b2s[tid] = __ldg(&b2[tid]);
    for (int i = tid; i < 64 * HID; i += 512) {
        int nl = i >> 4, f = i & 15;
        int node = node0 + nl;
        float v = 0.f;
        if (node < NN) {
            int gi = node * HID + f;
            v = g_dinv[node] * (g_agg2[gi] + g_h2s[gi]);
        }
        vsh[nl * VS_STRIDE + f] = v;
    }
    __syncthreads();

    int n = tid >> 3, og = tid & 7;
    int node = node0 + n;
    if (node >= NN) return;

    float acc[4][4];
    #pragma unroll
    for (int j = 0; j < 4; j++)
        #pragma unroll
        for (int i = 0; i < 4; i++)
            acc[j][i] = b2s[og * 4 + 32 * j + i];

    #pragma unroll
    for (int k = 0; k < HID; k++) {
        float v = vsh[n * VS_STRIDE + k];
        #pragma unroll
        for (int j = 0; j < 4; j++) {
            float4 w = *(const float4*)&wsh[k * FIN + og * 4 + 32 * j];
            acc[j][0] += v * w.x;  acc[j][1] += v * w.y;
            acc[j][2] += v * w.z;  acc[j][3] += v * w.w;
        }
    }
    float* orow = out + (size_t)node * FIN;
    #pragma unroll
    for (int j = 0; j < 4; j++)
        *(float4*)&orow[og * 4 + 32 * j] =
            make_float4(acc[j][0], acc[j][1], acc[j][2], acc[j][3]);
}

// ---------------------------------------------------------------------------
extern "C" void kernel_launch(void* const* d_in, const int* in_sizes, int n_in,
                              void* d_out, int out_size) {
    // Binding proven in R9: 0:x  1:edge_index(int32 [2,E])  2:W1  3:b1  4:W2  5:b2
    const float* x  = (const float*)d_in[0];
    const int*   ei = (const int*)d_in[1];
    const float* W1 = (const float*)d_in[2];
    const float* b1 = (const float*)d_in[3];
    const float* W2 = (const float*)d_in[4];
    const float* b2 = (const float*)d_in[5];
    float* out = (float*)d_out;

    k_init <<<(NN * HID / 4 + 255) / 256, 256>>>();
    k_deg  <<<(EMAX / 4 + 255) / 256, 256>>>(ei);
    k_mm1  <<<(NN + 31) / 32, 256>>>(x, W1);
    k_scat1<<<(EMAX + 255) / 256, 256>>>(ei);
    k_relu <<<(NN * HID + 255) / 256, 256>>>(b1);
    k_scat2<<<(EMAX + 255) / 256, 256>>>(ei);
    k_out  <<<(NN + 63) / 64, 512>>>(W2, b2, out);
}